// round 1
// baseline (speedup 1.0000x reference)
#include <cuda_runtime.h>
#include <math.h>

#define BB 32
#define TT 256
#define VV 4096
#define NROWS (BB * TT)

__device__ float g_rowC[NROWS];  // m + logZ per row
__device__ float g_ent[NROWS];   // entropy per row
__device__ float g_g[NROWS];     // final per-row scale

// ---------------------------------------------------------------------------
// Kernel 1: per-row softmax stats + entropy. One block (256 thr) per row.
// Each thread holds 16 floats in registers (4x float4).
// ---------------------------------------------------------------------------
__global__ __launch_bounds__(256) void rowstats_kernel(const float* __restrict__ logits) {
    const int row = blockIdx.x;
    const int tid = threadIdx.x;
    const float4* in = (const float4*)(logits + (size_t)row * VV);

    float4 v[4];
#pragma unroll
    for (int i = 0; i < 4; i++) v[i] = in[tid + 256 * i];

    float m = -1e30f;
#pragma unroll
    for (int i = 0; i < 4; i++)
        m = fmaxf(m, fmaxf(fmaxf(v[i].x, v[i].y), fmaxf(v[i].z, v[i].w)));

    __shared__ float redm[8];
    __shared__ float redZ[8];
    __shared__ float redS[8];

    // warp-reduce max
#pragma unroll
    for (int o = 16; o > 0; o >>= 1)
        m = fmaxf(m, __shfl_xor_sync(0xffffffffu, m, o));
    if ((tid & 31) == 0) redm[tid >> 5] = m;
    __syncthreads();
    {
        float t2 = redm[0];
#pragma unroll
        for (int i = 1; i < 8; i++) t2 = fmaxf(t2, redm[i]);
        m = t2;
    }

    float Z = 0.f, S = 0.f;
#pragma unroll
    for (int i = 0; i < 4; i++) {
        float xs[4] = {v[i].x, v[i].y, v[i].z, v[i].w};
#pragma unroll
        for (int j = 0; j < 4; j++) {
            float d = xs[j] - m;
            float e = __expf(d);
            Z += e;
            S = fmaf(e, d, S);
        }
    }
#pragma unroll
    for (int o = 16; o > 0; o >>= 1) {
        Z += __shfl_xor_sync(0xffffffffu, Z, o);
        S += __shfl_xor_sync(0xffffffffu, S, o);
    }
    if ((tid & 31) == 0) { redZ[tid >> 5] = Z; redS[tid >> 5] = S; }
    __syncthreads();

    if (tid == 0) {
        float Zt = 0.f, St = 0.f;
#pragma unroll
        for (int i = 0; i < 8; i++) { Zt += redZ[i]; St += redS[i]; }
        float logZ = logf(Zt);
        g_rowC[row] = m + logZ;
        g_ent[row]  = logZ - St / Zt;   // entropy = logZ - E[x-m]
    }
}

// ---------------------------------------------------------------------------
// Kernel 2: tiny MLP + sigmoid flags + sequential cumprod. One block / batch.
// ---------------------------------------------------------------------------
__global__ __launch_bounds__(256) void flags_kernel(const float* __restrict__ w1,
                                                    const float* __restrict__ b1,
                                                    const float* __restrict__ w2,
                                                    const float* __restrict__ b2) {
    const int b = blockIdx.x;
    const int t = threadIdx.x;

    __shared__ float sw1[128], sb1[128], sw2[128];
    __shared__ float sflag[TT];  // sflag[t] = flags[t+1]  (t=0..T-1; sflag[T-1]=1)

    if (t < 128) { sw1[t] = w1[t]; sb1[t] = b1[t]; sw2[t] = w2[t]; }
    __syncthreads();

    float f = 1.0f;  // flags[T] = 1
    if (t < TT - 1) {
        float e = g_ent[b * TT + t];
        const float entropy_max = logf((float)TT);
        float norm = 2.0f * e / entropy_max - 1.0f;
        float lin = 0.f;
#pragma unroll 8
        for (int j = 0; j < 128; j++) {
            float h = fmaxf(fmaf(norm, sw1[j], sb1[j]), 0.f);
            lin = fmaf(h, sw2[j], lin);
        }
        lin = 2.0f * lin + b2[0];
        float ns = (float)(TT - 1 - t);   // ns = T-1, T-2, ..., 1
        float zarg = lin - logf(ns);
        f = 1.0f / (1.0f + expf(-zarg));  // sigmoid
    }
    if (t < TT) sflag[t] = f;
    __syncthreads();

    if (t == 0) {
        // residual[s] = prod_{u=0..s-1} (1 - sflag[u]);  g[s] = sflag[s] * residual[s]
        float res = 1.0f;
        for (int s = 0; s < TT; s++) {
            g_g[b * TT + s] = sflag[s] * res;
            res *= (1.0f - sflag[s]);
        }
    }
}

// ---------------------------------------------------------------------------
// Kernel 3: out = exp(x - (m+logZ)) * g[row]. One block (256 thr) per row.
// ---------------------------------------------------------------------------
__global__ __launch_bounds__(256) void scale_kernel(const float* __restrict__ logits,
                                                    float* __restrict__ out) {
    const int row = blockIdx.x;
    const int tid = threadIdx.x;
    const float c  = g_rowC[row];
    const float gg = g_g[row];
    const float4* in = (const float4*)(logits + (size_t)row * VV);
    float4* o = (float4*)(out + (size_t)row * VV);

#pragma unroll
    for (int i = 0; i < 4; i++) {
        float4 v = in[tid + 256 * i];
        float4 r;
        r.x = __expf(v.x - c) * gg;
        r.y = __expf(v.y - c) * gg;
        r.z = __expf(v.z - c) * gg;
        r.w = __expf(v.w - c) * gg;
        o[tid + 256 * i] = r;
    }
}

// ---------------------------------------------------------------------------
extern "C" void kernel_launch(void* const* d_in, const int* in_sizes, int n_in,
                              void* d_out, int out_size) {
    const float* logits = (const float*)d_in[0];
    const float* w1     = (const float*)d_in[1];
    const float* b1     = (const float*)d_in[2];
    const float* w2     = (const float*)d_in[3];
    const float* b2     = (const float*)d_in[4];
    float* out          = (float*)d_out;

    rowstats_kernel<<<NROWS, 256>>>(logits);
    flags_kernel<<<BB, 256>>>(w1, b1, w2, b2);
    scale_kernel<<<NROWS, 256>>>(logits, out);
}

// round 2
// speedup vs baseline: 1.0687x; 1.0687x over previous
#include <cuda_runtime.h>
#include <math.h>

#define BB 32
#define TT 256
#define VV 4096
#define NROWS (BB * TT)

__device__ float g_rowC[NROWS];  // m + logZ per row
__device__ float g_ent[NROWS];   // entropy per row
__device__ float g_g[NROWS];     // final per-row scale

// ---------------------------------------------------------------------------
// Kernel 1: per-row softmax stats + entropy. One block (256 thr) per row.
// Each thread holds 16 floats in registers (4x float4). Normal loads so the
// data lands in L2 for kernel 3 to reuse (read in reverse there).
// ---------------------------------------------------------------------------
__global__ __launch_bounds__(256) void rowstats_kernel(const float* __restrict__ logits) {
    const int row = blockIdx.x;
    const int tid = threadIdx.x;
    const float4* in = (const float4*)(logits + (size_t)row * VV);

    float4 v[4];
#pragma unroll
    for (int i = 0; i < 4; i++) v[i] = in[tid + 256 * i];

    float m = -1e30f;
#pragma unroll
    for (int i = 0; i < 4; i++)
        m = fmaxf(m, fmaxf(fmaxf(v[i].x, v[i].y), fmaxf(v[i].z, v[i].w)));

    __shared__ float redm[8];
    __shared__ float redZ[8];
    __shared__ float redS[8];

#pragma unroll
    for (int o = 16; o > 0; o >>= 1)
        m = fmaxf(m, __shfl_xor_sync(0xffffffffu, m, o));
    if ((tid & 31) == 0) redm[tid >> 5] = m;
    __syncthreads();
    {
        float t2 = redm[0];
#pragma unroll
        for (int i = 1; i < 8; i++) t2 = fmaxf(t2, redm[i]);
        m = t2;
    }

    float Z = 0.f, S = 0.f;
#pragma unroll
    for (int i = 0; i < 4; i++) {
        float xs[4] = {v[i].x, v[i].y, v[i].z, v[i].w};
#pragma unroll
        for (int j = 0; j < 4; j++) {
            float d = xs[j] - m;
            float e = __expf(d);
            Z += e;
            S = fmaf(e, d, S);
        }
    }
#pragma unroll
    for (int o = 16; o > 0; o >>= 1) {
        Z += __shfl_xor_sync(0xffffffffu, Z, o);
        S += __shfl_xor_sync(0xffffffffu, S, o);
    }
    if ((tid & 31) == 0) { redZ[tid >> 5] = Z; redS[tid >> 5] = S; }
    __syncthreads();

    if (tid == 0) {
        float Zt = 0.f, St = 0.f;
#pragma unroll
        for (int i = 0; i < 8; i++) { Zt += redZ[i]; St += redS[i]; }
        float logZ = logf(Zt);
        g_rowC[row] = m + logZ;
        g_ent[row]  = logZ - St / Zt;   // entropy = logZ - E[x-m]
    }
}

// ---------------------------------------------------------------------------
// Kernel 2: tiny MLP + sigmoid flags + sequential cumprod. One block / batch.
// ---------------------------------------------------------------------------
__global__ __launch_bounds__(256) void flags_kernel(const float* __restrict__ w1,
                                                    const float* __restrict__ b1,
                                                    const float* __restrict__ w2,
                                                    const float* __restrict__ b2) {
    const int b = blockIdx.x;
    const int t = threadIdx.x;

    __shared__ float sw1[128], sb1[128], sw2[128];
    __shared__ float sflag[TT];  // sflag[t] = flags[t+1]  (t=0..T-1; sflag[T-1]=1)

    if (t < 128) { sw1[t] = w1[t]; sb1[t] = b1[t]; sw2[t] = w2[t]; }
    __syncthreads();

    float f = 1.0f;  // flags[T] = 1
    if (t < TT - 1) {
        float e = g_ent[b * TT + t];
        const float entropy_max = logf((float)TT);
        float norm = 2.0f * e / entropy_max - 1.0f;
        float lin = 0.f;
#pragma unroll 8
        for (int j = 0; j < 128; j++) {
            float h = fmaxf(fmaf(norm, sw1[j], sb1[j]), 0.f);
            lin = fmaf(h, sw2[j], lin);
        }
        lin = 2.0f * lin + b2[0];
        float ns = (float)(TT - 1 - t);   // ns = T-1, T-2, ..., 1
        float zarg = lin - logf(ns);
        f = 1.0f / (1.0f + expf(-zarg));  // sigmoid
    }
    if (t < TT) sflag[t] = f;
    __syncthreads();

    if (t == 0) {
        float res = 1.0f;
        for (int s = 0; s < TT; s++) {
            g_g[b * TT + s] = sflag[s] * res;
            res *= (1.0f - sflag[s]);
        }
    }
}

// ---------------------------------------------------------------------------
// Kernel 3: out = exp(x - (m+logZ)) * g[row]. One block (256 thr) per row.
// Rows processed in REVERSE launch order: the rows K1 touched last are the
// hottest in L2 (LRU), so early K3 blocks hit L2 instead of HBM.
// Logits reads use evict-first (.cs): last use, don't displace hot rows.
// Output stores use streaming (.cs): never re-read, don't pollute L2.
// ---------------------------------------------------------------------------
__global__ __launch_bounds__(256) void scale_kernel(const float* __restrict__ logits,
                                                    float* __restrict__ out) {
    const int row = NROWS - 1 - blockIdx.x;   // reverse order for L2 reuse
    const int tid = threadIdx.x;
    const float c  = g_rowC[row];
    const float gg = g_g[row];
    const float4* in = (const float4*)(logits + (size_t)row * VV);
    float4* o = (float4*)(out + (size_t)row * VV);

#pragma unroll
    for (int i = 0; i < 4; i++) {
        float4 v = __ldcs(&in[tid + 256 * i]);   // evict-first read (last use)
        float4 r;
        r.x = __expf(v.x - c) * gg;
        r.y = __expf(v.y - c) * gg;
        r.z = __expf(v.z - c) * gg;
        r.w = __expf(v.w - c) * gg;
        __stcs(&o[tid + 256 * i], r);            // streaming store
    }
}

// ---------------------------------------------------------------------------
extern "C" void kernel_launch(void* const* d_in, const int* in_sizes, int n_in,
                              void* d_out, int out_size) {
    const float* logits = (const float*)d_in[0];
    const float* w1     = (const float*)d_in[1];
    const float* b1     = (const float*)d_in[2];
    const float* w2     = (const float*)d_in[3];
    const float* b2     = (const float*)d_in[4];
    float* out          = (float*)d_out;

    rowstats_kernel<<<NROWS, 256>>>(logits);
    flags_kernel<<<BB, 256>>>(w1, b1, w2, b2);
    scale_kernel<<<NROWS, 256>>>(logits, out);
}